// round 7
// baseline (speedup 1.0000x reference)
#include <cuda_runtime.h>

#define B_    2048
#define FS_   32
#define FA_   16
#define T_    512
#define H_    64
#define SQRT_DT_ 0.22360679774997896f
#define MIN_V_  (-5.0f)
#define MAX_V_  (5.0f)

typedef unsigned long long u64;

__device__ __forceinline__ u64 pack2(float lo, float hi) {
    u64 r; asm("mov.b64 %0, {%1, %2};" : "=l"(r) : "f"(lo), "f"(hi)); return r;
}
__device__ __forceinline__ float2 unpack2(u64 v) {
    float2 f; asm("mov.b64 {%0, %1}, %2;" : "=f"(f.x), "=f"(f.y) : "l"(v)); return f;
}
// packed dual fp32 FMA (sm_100+)
__device__ __forceinline__ u64 ffma2(u64 a, u64 b, u64 c) {
    u64 d; asm("fma.rn.f32x2 %0, %1, %2, %3;" : "=l"(d) : "l"(a), "l"(b), "l"(c)); return d;
}
// accurate tanh from ex2.approx + rcp.approx (~1e-7 abs err)
__device__ __forceinline__ float tanh_acc(float x) {
    float e, r;
    asm("ex2.approx.f32 %0, %1;" : "=f"(e) : "f"(x * 2.8853900817779268f)); // 2*log2(e)
    asm("rcp.approx.f32 %0, %1;" : "=f"(r) : "f"(e + 1.0f));
    return (e - 1.0f) * r;
}

// Block = 512 threads = 16 warps = 8 (f,g) pairs; 2 batch elements per pair,
// 16 per block, grid = 128 (single wave). Same dataflow as the 811us config
// but with 4 warps/SMSP (from 4 independent pairs) so stall windows overlap.
// Full weights register-resident per warp (~160 regs); one named barrier per
// step with a double-buffered exchange; both warps redundantly finalize x.
__global__ void __launch_bounds__(512, 1)
sde_kernel(const float* __restrict__ a_in,   // (B, FA, T)
           const float* __restrict__ x0,     // (B, FS)
           const float* __restrict__ noise,  // (T-1, B, FS)
           const float* __restrict__ Wf1, const float* __restrict__ bf1,
           const float* __restrict__ Wf2, const float* __restrict__ bf2,
           const float* __restrict__ Wg1, const float* __restrict__ bg1,
           const float* __restrict__ Wg2, const float* __restrict__ bg2,
           float* __restrict__ out)          // (B, FS, T)
{
    const int tid  = threadIdx.x;
    const int wid  = tid >> 5;
    const int lane = tid & 31;
    const int pair = wid >> 1;            // 0..7
    const bool is_g = (wid & 1) != 0;
    const int el0  = pair * 2;            // 2 elements per pair
    const int gb0  = blockIdx.x * 16 + el0;

    __shared__ __align__(16) float v_sm[16][2][64];       // per-warp x/h buffer (8KB)
    __shared__ __align__(16) float a_sg[2][16][4][16];    // a tiles, 4 steps, transposed (8KB)
    __shared__ __align__(16) float ex_sm[8][2][2][2][32]; // [pair][tb][role][e][lane] (8KB)

    const float* W1 = is_g ? Wg1 : Wf1;
    const float* b1 = is_g ? bg1 : bf1;
    const float* W2 = is_g ? Wg2 : Wf2;
    const float* b2 = is_g ? bg2 : bf2;

    // -------- register-resident weights, packed (k, k+1) over k --------
    u64 w1a[24], w1b[24], w2p[32];
#pragma unroll
    for (int kp = 0; kp < 24; kp++) {
        w1a[kp] = pack2(W1[(2*kp)*H_ + lane],      W1[(2*kp+1)*H_ + lane]);
        w1b[kp] = pack2(W1[(2*kp)*H_ + lane + 32], W1[(2*kp+1)*H_ + lane + 32]);
    }
#pragma unroll
    for (int kp = 0; kp < 32; kp++) {
        w2p[kp] = pack2(W2[(2*kp)*FS_ + lane], W2[(2*kp+1)*FS_ + lane]);
    }
    const float bias1a = b1[lane];
    const float bias1b = b1[lane + 32];
    const float bias2  = b2[lane];

    const float* a_base  = a_in  + (size_t)gb0 * (FA_*T_) + (size_t)(lane >> 1) * T_ + (lane & 1) * 2;
    const float* nz_base = noise + (size_t)gb0 * FS_ + lane;
    float*       out_b   = out   + (size_t)gb0 * (FS_*T_) + (size_t)lane * T_;

    float2 areg[2];
    float  eps_n[2];

    // -------- prologue --------
#pragma unroll
    for (int e = 0; e < 2; e++) {
        float xv = x0[(size_t)(gb0 + e) * FS_ + lane];
        v_sm[wid][e][lane] = xv;
        if (!is_g) out_b[(size_t)e * (FS_*T_)] = xv;
    }
    if (!is_g) {
#pragma unroll
        for (int e = 0; e < 2; e++) {
            float2 v = *reinterpret_cast<const float2*>(a_base + (size_t)e * (FA_*T_));
            a_sg[0][el0 + e][(lane & 1)*2 + 0][lane >> 1] = v.x;
            a_sg[0][el0 + e][(lane & 1)*2 + 1][lane >> 1] = v.y;
        }
#pragma unroll
        for (int e = 0; e < 2; e++)
            areg[e] = *reinterpret_cast<const float2*>(a_base + (size_t)e * (FA_*T_) + 4);
    } else {
#pragma unroll
        for (int e = 0; e < 2; e++) eps_n[e] = nz_base[e * FS_];
    }
    __syncthreads();

    const int bar_id = 1 + pair;          // 8 named barriers, 64 threads each

#pragma unroll 1
    for (int t = 1; t < T_; t++) {
        const int ai  = t - 1;
        const int tb  = t & 1;
        const int g4  = ai >> 2;
        const int buf = g4 & 1;
        const int sl  = ai & 3;

        // g: rotate noise double-buffer; issue next load early
        float eps_u[2];
        if (is_g) {
#pragma unroll
            for (int e = 0; e < 2; e++) eps_u[e] = eps_n[e];
            if (t < T_ - 1) {
                const float* np = nz_base + (size_t)t * (B_ * FS_);
#pragma unroll
                for (int e = 0; e < 2; e++) eps_n[e] = np[e * FS_];
            }
        }

        // ---------------- layer 1 (48 -> 64), 4 chains ----------------
        u64 aa[2], ab[2];
#pragma unroll
        for (int e = 0; e < 2; e++) { aa[e] = 0ull; ab[e] = 0ull; }
#pragma unroll
        for (int e = 0; e < 2; e++) {
            const ulonglong2* ap = reinterpret_cast<const ulonglong2*>(&a_sg[buf][el0+e][sl][0]);
            const ulonglong2* xp = reinterpret_cast<const ulonglong2*>(&v_sm[wid][e][0]);
#pragma unroll
            for (int q = 0; q < 4; q++) {            // s[0:16) = a_t
                ulonglong2 v = ap[q];
                aa[e] = ffma2(v.x, w1a[2*q],   aa[e]);
                aa[e] = ffma2(v.y, w1a[2*q+1], aa[e]);
                ab[e] = ffma2(v.x, w1b[2*q],   ab[e]);
                ab[e] = ffma2(v.y, w1b[2*q+1], ab[e]);
            }
#pragma unroll
            for (int q = 0; q < 8; q++) {            // s[16:48) = x_t
                ulonglong2 v = xp[q];
                aa[e] = ffma2(v.x, w1a[8+2*q], aa[e]);
                aa[e] = ffma2(v.y, w1a[9+2*q], aa[e]);
                ab[e] = ffma2(v.x, w1b[8+2*q], ab[e]);
                ab[e] = ffma2(v.y, w1b[9+2*q], ab[e]);
            }
        }
        // tanh + stash h in private buffer (overwrites x)
#pragma unroll
        for (int e = 0; e < 2; e++) {
            float2 u = unpack2(aa[e]);
            float2 v = unpack2(ab[e]);
            v_sm[wid][e][lane]      = tanh_acc(u.x + u.y + bias1a);
            v_sm[wid][e][lane + 32] = tanh_acc(v.x + v.y + bias1b);
        }
        __syncwarp();

        // ---------------- layer 2 (64 -> 32), 4 chains ----------------
        float o[2];
#pragma unroll
        for (int e = 0; e < 2; e++) {
            const ulonglong2* hp = reinterpret_cast<const ulonglong2*>(&v_sm[wid][e][0]);
            u64 c0 = 0ull, c1 = 0ull;
#pragma unroll
            for (int q = 0; q < 16; q++) {
                ulonglong2 v = hp[q];
                c0 = ffma2(v.x, w2p[2*q],   c0);
                c1 = ffma2(v.y, w2p[2*q+1], c1);
            }
            float2 u0 = unpack2(c0), u1 = unpack2(c1);
            o[e] = (u0.x + u0.y) + (u1.x + u1.y) + bias2;
        }

        // publish: f -> o_f (incl. bias), g -> full diffusion term d
        if (!is_g) {
#pragma unroll
            for (int e = 0; e < 2; e++) ex_sm[pair][tb][0][e][lane] = o[e];
        } else {
#pragma unroll
            for (int e = 0; e < 2; e++) ex_sm[pair][tb][1][e][lane] = o[e] * (eps_u[e] * SQRT_DT_);
        }

        // f: a-tile staging pre-barrier (fills partner-wait window)
        if (!is_g) {
            if (sl == 2 && g4 + 1 < 128) {
#pragma unroll
                for (int e = 0; e < 2; e++) {
                    a_sg[buf ^ 1][el0 + e][(lane & 1)*2 + 0][lane >> 1] = areg[e].x;
                    a_sg[buf ^ 1][el0 + e][(lane & 1)*2 + 1][lane >> 1] = areg[e].y;
                }
            }
            if (sl == 3 && g4 + 2 < 128) {
                const float* ap = a_base + (size_t)(g4 + 2) * 4;
#pragma unroll
                for (int e = 0; e < 2; e++)
                    areg[e] = *reinterpret_cast<const float2*>(ap + (size_t)e * (FA_*T_));
            }
        }

        asm volatile("bar.sync %0, 64;" :: "r"(bar_id) : "memory");

        // both warps redundantly finalize x into their own buffer
#pragma unroll
        for (int e = 0; e < 2; e++) {
            float xv = ex_sm[pair][tb][0][e][lane] + ex_sm[pair][tb][1][e][lane];
            xv = fminf(fmaxf(xv, MIN_V_), MAX_V_);
            v_sm[wid][e][lane] = xv;                  // overwrite h with new x
            if (!is_g) out_b[(size_t)e * (FS_*T_) + t] = xv;
        }
        __syncwarp();
    }
}

extern "C" void kernel_launch(void* const* d_in, const int* in_sizes, int n_in,
                              void* d_out, int out_size) {
    (void)in_sizes; (void)n_in; (void)out_size;
    // metadata order: ts, in_signal, x0, noise, Wf1, bf1, Wf2, bf2, Wg1, bg1, Wg2, bg2
    const float* a_in  = (const float*)d_in[1];
    const float* x0    = (const float*)d_in[2];
    const float* noise = (const float*)d_in[3];
    const float* Wf1   = (const float*)d_in[4];
    const float* bf1   = (const float*)d_in[5];
    const float* Wf2   = (const float*)d_in[6];
    const float* bf2   = (const float*)d_in[7];
    const float* Wg1   = (const float*)d_in[8];
    const float* bg1   = (const float*)d_in[9];
    const float* Wg2   = (const float*)d_in[10];
    const float* bg2   = (const float*)d_in[11];
    float* out = (float*)d_out;

    sde_kernel<<<B_ / 16, 512>>>(a_in, x0, noise,
                                 Wf1, bf1, Wf2, bf2,
                                 Wg1, bg1, Wg2, bg2,
                                 out);
}

// round 8
// speedup vs baseline: 1.7135x; 1.7135x over previous
#include <cuda_runtime.h>

#define B_    2048
#define FS_   32
#define FA_   16
#define T_    512
#define H_    64
#define SQRT_DT_ 0.22360679774997896f
#define MIN_V_  (-5.0f)
#define MAX_V_  (5.0f)

typedef unsigned long long u64;

__device__ __forceinline__ u64 pack2(float lo, float hi) {
    u64 r; asm("mov.b64 %0, {%1, %2};" : "=l"(r) : "f"(lo), "f"(hi)); return r;
}
__device__ __forceinline__ float2 unpack2(u64 v) {
    float2 f; asm("mov.b64 {%0, %1}, %2;" : "=f"(f.x), "=f"(f.y) : "l"(v)); return f;
}
// packed dual fp32 FMA (sm_100+)
__device__ __forceinline__ u64 ffma2(u64 a, u64 b, u64 c) {
    u64 d; asm("fma.rn.f32x2 %0, %1, %2, %3;" : "=l"(d) : "l"(a), "l"(b), "l"(c)); return d;
}
// accurate tanh from ex2.approx + rcp.approx (~1e-7 abs err)
__device__ __forceinline__ float tanh_acc(float x) {
    float e, r;
    asm("ex2.approx.f32 %0, %1;" : "=f"(e) : "f"(x * 2.8853900817779268f)); // 2*log2(e)
    asm("rcp.approx.f32 %0, %1;" : "=f"(r) : "f"(e + 1.0f));
    return (e - 1.0f) * r;
}

// J-SPLIT design. Block = 256 threads = 8 warps = 2 groups of 4 warps.
// Group roles: 0=(f,j0) 1=(f,j1) 2=(g,j0) 3=(g,j1). Each warp computes its
// MLP's hidden HALF h[jh*32+lane] (W1-half: 48 regs) and the L2 partial over
// k = its own j-half (W2-half: 32 regs) -- so L2 consumes only the h this
// warp produced: no intra-MLP barrier. The 4 partials (+eps) are summed in
// the per-group finalize after ONE named barrier. 80 weight regs/thread
// leaves ~140 free registers for deep LDS hoisting (the R2-config killer).
// Group owns 8 elements; 16/block; grid=128 (single wave, 2 warps/SMSP).
__global__ void __launch_bounds__(256, 1)
sde_kernel(const float* __restrict__ a_in,   // (B, FA, T)
           const float* __restrict__ x0,     // (B, FS)
           const float* __restrict__ noise,  // (T-1, B, FS)
           const float* __restrict__ Wf1, const float* __restrict__ bf1,
           const float* __restrict__ Wf2, const float* __restrict__ bf2,
           const float* __restrict__ Wg1, const float* __restrict__ bg1,
           const float* __restrict__ Wg2, const float* __restrict__ bg2,
           float* __restrict__ out)          // (B, FS, T)
{
    const int tid  = threadIdx.x;
    const int wid  = tid >> 5;
    const int lane = tid & 31;
    const int grp  = wid >> 2;            // 0..1
    const int role = wid & 3;             // 0=(f,0) 1=(f,1) 2=(g,0) 3=(g,1)
    const int jb   = (role & 1) * 32;     // j-half base (= L2 k-half base)
    const int el0  = grp * 8;
    const int gb0  = blockIdx.x * 16 + el0;

    __shared__ __align__(16) float v_sm[8][8][32];        // per-warp x / h-half (8KB)
    __shared__ __align__(16) float a_sg[2][16][4][16];    // a tiles, 4 steps, transposed (8KB)
    __shared__ __align__(16) float ex_sm[2][2][5][8][32]; // [tb][grp][slot][e][lane] (25.6KB)
                                                          // slots 0..3 = partials, 4 = eps*sqrt(dt)

    const float* W1 = (role >> 1) ? Wg1 : Wf1;
    const float* B1 = (role >> 1) ? bg1 : bf1;
    const float* W2 = (role >> 1) ? Wg2 : Wf2;

    // ---- register-resident weight halves (80 regs) ----
    u64 w1h[24];   // W1[k][jb+lane], k-paired over 48 inputs
#pragma unroll
    for (int kp = 0; kp < 24; kp++)
        w1h[kp] = pack2(W1[(2*kp)*H_ + jb + lane], W1[(2*kp+1)*H_ + jb + lane]);
    u64 w2h[16];   // W2[jb+k][lane], k-paired over this warp's 32-k half
#pragma unroll
    for (int kp = 0; kp < 16; kp++)
        w2h[kp] = pack2(W2[(jb + 2*kp)*FS_ + lane], W2[(jb + 2*kp + 1)*FS_ + lane]);

    const float b1v   = B1[jb + lane];
    // fold layer-2 biases into one partial per MLP (role 0 carries bf2, role 2 bg2)
    const float pbias = (role == 0) ? bf2[lane] : ((role == 2) ? bg2[lane] : 0.0f);

    const float* a_base  = a_in  + (size_t)gb0 * (FA_*T_) + (size_t)(lane >> 1) * T_ + (lane & 1) * 2;
    const float* nz_base = noise + (size_t)gb0 * FS_ + lane;
    float*       out_b   = out   + (size_t)gb0 * (FS_*T_) + (size_t)lane * T_;

    float2 areg[8];    // role 1: prefetched a-tiles
    float  eps_n[8];   // role 3: next-step noise

    // -------- prologue --------
#pragma unroll
    for (int e = 0; e < 8; e++) {
        float xv = x0[(size_t)(gb0 + e) * FS_ + lane];
        v_sm[wid][e][lane] = xv;
        if (role == 0) out_b[(size_t)e * (FS_*T_)] = xv;
    }
    if (role == 1) {   // a staging: group 0 into buffer 0, group 1 into regs
#pragma unroll
        for (int e = 0; e < 8; e++) {
            float2 v = *reinterpret_cast<const float2*>(a_base + (size_t)e * (FA_*T_));
            a_sg[0][el0 + e][(lane & 1)*2 + 0][lane >> 1] = v.x;
            a_sg[0][el0 + e][(lane & 1)*2 + 1][lane >> 1] = v.y;
        }
#pragma unroll
        for (int e = 0; e < 8; e++)
            areg[e] = *reinterpret_cast<const float2*>(a_base + (size_t)e * (FA_*T_) + 4);
    }
    if (role == 3) {
#pragma unroll
        for (int e = 0; e < 8; e++) eps_n[e] = nz_base[e * FS_];
    }
    __syncthreads();

    const int bar_id = 1 + grp;           // 128-thread group barrier

#pragma unroll 1
    for (int t = 1; t < T_; t++) {
        const int ai  = t - 1;
        const int tb  = t & 1;
        const int g4  = ai >> 2;
        const int buf = g4 & 1;
        const int sl  = ai & 3;

        // role 3: rotate noise double-buffer; issue next loads early
        float eps_u[8];
        if (role == 3) {
#pragma unroll
            for (int e = 0; e < 8; e++) eps_u[e] = eps_n[e];
            if (t < T_ - 1) {
                const float* np = nz_base + (size_t)t * (B_ * FS_);
#pragma unroll
                for (int e = 0; e < 8; e++) eps_n[e] = np[e * FS_];
            }
        }

        // ------- layer 1 half: h[jb+lane] for 8 elements (8 chains) -------
        u64 acc[8];
#pragma unroll
        for (int e = 0; e < 8; e++) acc[e] = 0ull;
#pragma unroll
        for (int e = 0; e < 8; e++) {
            const ulonglong2* ap = reinterpret_cast<const ulonglong2*>(&a_sg[buf][el0+e][sl][0]);
            const ulonglong2* xp = reinterpret_cast<const ulonglong2*>(&v_sm[wid][e][0]);
#pragma unroll
            for (int q = 0; q < 4; q++) {            // s[0:16) = a_t
                ulonglong2 v = ap[q];
                acc[e] = ffma2(v.x, w1h[2*q],   acc[e]);
                acc[e] = ffma2(v.y, w1h[2*q+1], acc[e]);
            }
#pragma unroll
            for (int q = 0; q < 8; q++) {            // s[16:48) = x_t
                ulonglong2 v = xp[q];
                acc[e] = ffma2(v.x, w1h[8+2*q], acc[e]);
                acc[e] = ffma2(v.y, w1h[9+2*q], acc[e]);
            }
        }
        // tanh + stash h-half in private buffer (overwrites x)
#pragma unroll
        for (int e = 0; e < 8; e++) {
            float2 u = unpack2(acc[e]);
            v_sm[wid][e][lane] = tanh_acc(u.x + u.y + b1v);
        }
        __syncwarp();

        // ------- layer 2 partial over own k-half (8 chains) -------
#pragma unroll
        for (int e = 0; e < 8; e++) {
            const ulonglong2* hp = reinterpret_cast<const ulonglong2*>(&v_sm[wid][e][0]);
            u64 c = 0ull;
#pragma unroll
            for (int q = 0; q < 8; q++) {
                ulonglong2 v = hp[q];
                c = ffma2(v.x, w2h[2*q],   c);
                c = ffma2(v.y, w2h[2*q+1], c);
            }
            float2 u = unpack2(c);
            ex_sm[tb][grp][role][e][lane] = u.x + u.y + pbias;
        }
        if (role == 3) {
#pragma unroll
            for (int e = 0; e < 8; e++)
                ex_sm[tb][grp][4][e][lane] = eps_u[e] * SQRT_DT_;
        }

        // role 1: a-tile staging pre-barrier (fills partner-wait window)
        if (role == 1) {
            if (sl == 2 && g4 + 1 < 128) {
#pragma unroll
                for (int e = 0; e < 8; e++) {
                    a_sg[buf ^ 1][el0 + e][(lane & 1)*2 + 0][lane >> 1] = areg[e].x;
                    a_sg[buf ^ 1][el0 + e][(lane & 1)*2 + 1][lane >> 1] = areg[e].y;
                }
            }
            if (sl == 3 && g4 + 2 < 128) {
                const float* ap = a_base + (size_t)(g4 + 2) * 4;
#pragma unroll
                for (int e = 0; e < 8; e++)
                    areg[e] = *reinterpret_cast<const float2*>(ap + (size_t)e * (FA_*T_));
            }
        }

        asm volatile("bar.sync %0, 128;" :: "r"(bar_id) : "memory");

        // ------- all 4 warps redundantly finalize x into own buffer -------
#pragma unroll
        for (int e = 0; e < 8; e++) {
            float p0 = ex_sm[tb][grp][0][e][lane];
            float p1 = ex_sm[tb][grp][1][e][lane];
            float p2 = ex_sm[tb][grp][2][e][lane];
            float p3 = ex_sm[tb][grp][3][e][lane];
            float es = ex_sm[tb][grp][4][e][lane];
            float xv = (p0 + p1) + (p2 + p3) * es;
            xv = fminf(fmaxf(xv, MIN_V_), MAX_V_);
            v_sm[wid][e][lane] = xv;                  // overwrite h with new x
            if (role == 0) out_b[(size_t)e * (FS_*T_) + t] = xv;
        }
        __syncwarp();
    }
}

extern "C" void kernel_launch(void* const* d_in, const int* in_sizes, int n_in,
                              void* d_out, int out_size) {
    (void)in_sizes; (void)n_in; (void)out_size;
    // metadata order: ts, in_signal, x0, noise, Wf1, bf1, Wf2, bf2, Wg1, bg1, Wg2, bg2
    const float* a_in  = (const float*)d_in[1];
    const float* x0    = (const float*)d_in[2];
    const float* noise = (const float*)d_in[3];
    const float* Wf1   = (const float*)d_in[4];
    const float* bf1   = (const float*)d_in[5];
    const float* Wf2   = (const float*)d_in[6];
    const float* bf2   = (const float*)d_in[7];
    const float* Wg1   = (const float*)d_in[8];
    const float* bg1   = (const float*)d_in[9];
    const float* Wg2   = (const float*)d_in[10];
    const float* bg2   = (const float*)d_in[11];
    float* out = (float*)d_out;

    sde_kernel<<<B_ / 16, 256>>>(a_in, x0, noise,
                                 Wf1, bf1, Wf2, bf2,
                                 Wg1, bg1, Wg2, bg2,
                                 out);
}